// round 10
// baseline (speedup 1.0000x reference)
#include <cuda_runtime.h>
#include <cuda_bf16.h>
#include <stdint.h>

#define NROWS 1024
#define NV    32000
#define LSRC  320
#define CTXL  256
#define STN   32
#define HDIM  512
#define SCALE 0.04419417382415922f   // 1/sqrt(512)

__device__ __nv_bfloat16 g_Wbf[(size_t)HDIM * NV];    // W bf16, [k][n]
__device__ __nv_bfloat16 g_Abf[(size_t)NROWS * HDIM]; // dec bf16, [m][k]
__device__ float g_copy4[4][NROWS][LSRC];             // split-K copy logit partials
__device__ float g_copye[NROWS][LSRC];                // exp'd copy values
__device__ float g_rsum[NROWS];                       // row sums (seeded with copy part)
__device__ unsigned g_cnt[8];                         // per-M-cohort arrival counters

// ---------------------------------------------------------------------------
// helpers (mma.sync only — tcgen05 rejected by harness's compute_103 stage)
// ---------------------------------------------------------------------------
__device__ __forceinline__ uint32_t smem_u32(const void* p) {
    return (uint32_t)__cvta_generic_to_shared(p);
}
__device__ __forceinline__ void cp_async16(uint32_t dst, const void* src) {
    asm volatile("cp.async.cg.shared.global [%0], [%1], 16;\n" :: "r"(dst), "l"(src));
}
__device__ __forceinline__ void cp_commit() {
    asm volatile("cp.async.commit_group;\n");
}
template <int N> __device__ __forceinline__ void cp_wait() {
    asm volatile("cp.async.wait_group %0;\n" :: "n"(N));
}
#define SWZ128(o) ((o) ^ (((o) >> 3) & 0x70))

__device__ __forceinline__ void ldsm_x4(uint32_t* r, uint32_t a) {
    asm volatile("ldmatrix.sync.aligned.m8n8.x4.shared.b16 {%0,%1,%2,%3}, [%4];\n"
                 : "=r"(r[0]), "=r"(r[1]), "=r"(r[2]), "=r"(r[3]) : "r"(a));
}
__device__ __forceinline__ void ldsm_x4_t(uint32_t* r, uint32_t a) {
    asm volatile("ldmatrix.sync.aligned.m8n8.x4.trans.shared.b16 {%0,%1,%2,%3}, [%4];\n"
                 : "=r"(r[0]), "=r"(r[1]), "=r"(r[2]), "=r"(r[3]) : "r"(a));
}
__device__ __forceinline__ void mma16816(float* c, const uint32_t* a, const uint32_t* b) {
    asm volatile(
        "mma.sync.aligned.m16n8k16.row.col.f32.bf16.bf16.f32 "
        "{%0,%1,%2,%3}, {%4,%5,%6,%7}, {%8,%9}, {%0,%1,%2,%3};\n"
        : "+f"(c[0]), "+f"(c[1]), "+f"(c[2]), "+f"(c[3])
        : "r"(a[0]), "r"(a[1]), "r"(a[2]), "r"(a[3]),
          "r"(b[0]), "r"(b[1]));
}

// ---------------------------------------------------------------------------
// Kernel A: copy-logit split-K partials + W/dec bf16 convert
// ---------------------------------------------------------------------------
#define CP_BLK 640
#define NW4 ((HDIM * (size_t)NV) / 4)
#define NA4 ((NROWS * (size_t)HDIM) / 4)
#define CV_BLK ((unsigned)((NW4 + NA4 + 255) / 256))

__global__ __launch_bounds__(256)
void prep_kernel(const float* __restrict__ W, const float* __restrict__ dec,
                 const float* __restrict__ src)
{
    const int bid = blockIdx.x;
    const int tid = threadIdx.x;

    if (bid < CP_BLK) {
        const int kq = bid & 3;
        const int rest = bid >> 2;
        const int st = rest % 5;
        const int r2 = rest / 5;
        const int lt = r2 & 3, b = r2 >> 2;

        __shared__ float sA[2][32][17];
        __shared__ float sB[2][64][17];

        const float* Ag = dec + (size_t)(b * 128 + lt * 32) * HDIM + kq * 128;
        const float* Bg = src + (size_t)(b * LSRC + st * 64) * HDIM + kq * 128;

        const int ar = tid >> 3;
        const int ac = (tid & 7) * 2;

        float2 ra = *(const float2*)(Ag + (size_t)ar * HDIM + ac);
        float2 rb0 = *(const float2*)(Bg + (size_t)ar * HDIM + ac);
        float2 rb1 = *(const float2*)(Bg + (size_t)(ar + 32) * HDIM + ac);
        sA[0][ar][ac] = ra.x;  sA[0][ar][ac + 1] = ra.y;
        sB[0][ar][ac] = rb0.x; sB[0][ar][ac + 1] = rb0.y;
        sB[0][ar + 32][ac] = rb1.x; sB[0][ar + 32][ac + 1] = rb1.y;
        __syncthreads();

        const int ty = tid >> 5;
        const int tx = tid & 31;
        float acc[4][2] = {};

        for (int kt = 0; kt < 8; ++kt) {
            const int buf = kt & 1;
            if (kt < 7) {
                const int k0 = (kt + 1) * 16;
                ra  = *(const float2*)(Ag + (size_t)ar * HDIM + k0 + ac);
                rb0 = *(const float2*)(Bg + (size_t)ar * HDIM + k0 + ac);
                rb1 = *(const float2*)(Bg + (size_t)(ar + 32) * HDIM + k0 + ac);
            }
            #pragma unroll
            for (int k = 0; k < 16; ++k) {
                float a0 = sA[buf][ty * 4 + 0][k];
                float a1 = sA[buf][ty * 4 + 1][k];
                float a2 = sA[buf][ty * 4 + 2][k];
                float a3 = sA[buf][ty * 4 + 3][k];
                float b0 = sB[buf][tx * 2 + 0][k];
                float b1 = sB[buf][tx * 2 + 1][k];
                acc[0][0] += a0 * b0; acc[0][1] += a0 * b1;
                acc[1][0] += a1 * b0; acc[1][1] += a1 * b1;
                acc[2][0] += a2 * b0; acc[2][1] += a2 * b1;
                acc[3][0] += a3 * b0; acc[3][1] += a3 * b1;
            }
            if (kt < 7) {
                const int nb = 1 - buf;
                sA[nb][ar][ac] = ra.x;  sA[nb][ar][ac + 1] = ra.y;
                sB[nb][ar][ac] = rb0.x; sB[nb][ar][ac + 1] = rb0.y;
                sB[nb][ar + 32][ac] = rb1.x; sB[nb][ar + 32][ac + 1] = rb1.y;
            }
            __syncthreads();
        }

        #pragma unroll
        for (int i = 0; i < 4; ++i) {
            const int row = b * 128 + lt * 32 + ty * 4 + i;
            #pragma unroll
            for (int j = 0; j < 2; ++j)
                g_copy4[kq][row][st * 64 + tx * 2 + j] = acc[i][j];
        }
    } else {
        const size_t gid = (size_t)(bid - CP_BLK) * 256 + tid;
        if (gid < NW4) {
            float4 v = ((const float4*)W)[gid];
            __nv_bfloat162 p0 = __floats2bfloat162_rn(v.x, v.y);
            __nv_bfloat162 p1 = __floats2bfloat162_rn(v.z, v.w);
            uint2 o = {*(uint32_t*)&p0, *(uint32_t*)&p1};
            ((uint2*)g_Wbf)[gid] = o;
        } else if (gid < NW4 + NA4) {
            const size_t i = gid - NW4;
            float4 v = ((const float4*)dec)[i];
            __nv_bfloat162 p0 = __floats2bfloat162_rn(v.x, v.y);
            __nv_bfloat162 p1 = __floats2bfloat162_rn(v.z, v.w);
            uint2 o = {*(uint32_t*)&p0, *(uint32_t*)&p1};
            ((uint2*)g_Abf)[i] = o;
        }
    }
}

// ---------------------------------------------------------------------------
// Kernel B: copy exps + seed row sums + zero cohort counters.
//   256 blocks x 320 threads, 4 rows each.
// ---------------------------------------------------------------------------
__global__ __launch_bounds__(320)
void copysum_kernel(const int* __restrict__ mask)
{
    const int t = threadIdx.x;
    if (blockIdx.x == 0 && t < 8) g_cnt[t] = 0;

    __shared__ float sred[10];
    for (int r = 0; r < 4; ++r) {
        const int row = blockIdx.x * 4 + r;
        const int b = row >> 7;
        float dot = g_copy4[0][row][t] + g_copy4[1][row][t]
                  + g_copy4[2][row][t] + g_copy4[3][row][t];
        float e = (mask[b * LSRC + t] == 0) ? 0.f : __expf(dot * SCALE);
        g_copye[row][t] = e;

        float w = e;
        #pragma unroll
        for (int off = 16; off > 0; off >>= 1)
            w += __shfl_xor_sync(0xffffffffu, w, off);
        if ((t & 31) == 0) sred[t >> 5] = w;
        __syncthreads();
        if (t == 0) {
            float s = 0.f;
            #pragma unroll
            for (int i = 0; i < 10; ++i) s += sred[i];
            g_rsum[row] = s;            // seed (plain store, pre-GEMM)
        }
        __syncthreads();
    }
}

// ---------------------------------------------------------------------------
// Kernel C: mma.sync gen GEMM, fused exp + row-sum + IN-KERNEL normalization.
//   BM=128 BN=256 BK=64, 256 thr (8 warps 2x4, warp tile 64x64), 3-stage
//   cp.async pipeline. Grid (125 N, 8 M): per-M-cohort counter; after the
//   cohort's 125 CTAs have summed, each CTA scales its in-register exps and
//   stores the FINAL normalized values (no separate norm pass).
//   Deadlock-safe: 125 contiguous bids < 148 SMs even at 1 CTA/SM.
// ---------------------------------------------------------------------------
#define KC 64
#define SA_BYTES 16384           // 128 rows * 128B (SW128)
#define SB_PITCH 528             // 512B data + 16B pad
#define SB_BYTES (64 * SB_PITCH) // 33792
#define STG (SA_BYTES + SB_BYTES)
#define DYN_BYTES (3 * STG + 1024)   // 151552

__global__ __launch_bounds__(256, 1)
void gemm_kernel(const float* __restrict__ bias, float* __restrict__ out)
{
    extern __shared__ char dyn[];
    __shared__ float sbias[256];

    const int tid  = threadIdx.x;
    const int warp = tid >> 5, lane = tid & 31;
    const int n0 = blockIdx.x * 256;
    const int m0 = blockIdx.y * 128;
    const int wm = (warp >> 2) * 64;     // 0 or 64
    const int wn = (warp & 3) * 64;      // 0,64,128,192
    const uint32_t base = (smem_u32(dyn) + 1023) & ~1023u;

    sbias[tid] = bias[n0 + tid];

    // loader mappings
    const int a_r = tid >> 1;            // 0..127
    const int a_h = (tid & 1) * 4;       // chunk base 0 or 4
    const int b_k = tid >> 2;            // 0..63
    const int b_q = tid & 3;             // chunk phase

    #define LOAD_CHUNK(c) do {                                                   \
        const int _s = (c) % 3;                                                  \
        const uint32_t _sa = base + _s * STG;                                    \
        const uint32_t _sb = _sa + SA_BYTES;                                     \
        _Pragma("unroll")                                                        \
        for (int _i = 0; _i < 4; ++_i) {                                         \
            const int _ch = a_h + _i;                                            \
            const uint32_t _ao = (uint32_t)(a_r * 128 + _ch * 16);               \
            cp_async16(_sa + SWZ128(_ao),                                        \
                       g_Abf + (size_t)(m0 + a_r) * HDIM + (c) * KC + _ch * 8);  \
        }                                                                        \
        _Pragma("unroll")                                                        \
        for (int _j = 0; _j < 8; ++_j) {                                         \
            const int _ch = b_q + _j * 4;                                        \
            cp_async16(_sb + b_k * SB_PITCH + _ch * 16,                          \
                       g_Wbf + (size_t)((c) * KC + b_k) * NV + n0 + _ch * 8);    \
        }                                                                        \
    } while (0)

    LOAD_CHUNK(0); cp_commit();
    LOAD_CHUNK(1); cp_commit();

    float acc[4][8][4];
    #pragma unroll
    for (int i = 0; i < 4; ++i)
        #pragma unroll
        for (int j = 0; j < 8; ++j)
            #pragma unroll
            for (int q = 0; q < 4; ++q) acc[i][j][q] = 0.f;

    const int KT = HDIM / KC;   // 8
    for (int kt = 0; kt < KT; ++kt) {
        if (kt < KT - 2) cp_wait<1>(); else cp_wait<0>();
        __syncthreads();

        if (kt + 2 < KT) LOAD_CHUNK(kt + 2);
        cp_commit();

        const int st = kt % 3;
        const uint32_t aS = base + st * STG;
        const uint32_t bS = aS + SA_BYTES;

        #pragma unroll
        for (int kk = 0; kk < 4; ++kk) {
            uint32_t af[4][4], bfr[8][2];
            #pragma unroll
            for (int mi = 0; mi < 4; ++mi) {
                const uint32_t off = (uint32_t)((wm + mi * 16 + (lane & 15)) * 128
                                                + kk * 32 + (lane >> 4) * 16);
                ldsm_x4(af[mi], aS + SWZ128(off));
            }
            #pragma unroll
            for (int g = 0; g < 4; ++g) {
                uint32_t r[4];
                const uint32_t addr = bS + (kk * 16 + (lane & 15)) * SB_PITCH
                                         + wn * 2 + g * 32 + (lane >> 4) * 16;
                ldsm_x4_t(r, addr);
                bfr[g * 2][0] = r[0];     bfr[g * 2][1] = r[1];
                bfr[g * 2 + 1][0] = r[2]; bfr[g * 2 + 1][1] = r[3];
            }
            #pragma unroll
            for (int mi = 0; mi < 4; ++mi)
                #pragma unroll
                for (int ni = 0; ni < 8; ++ni)
                    mma16816(acc[mi][ni], af[mi], bfr[ni]);
        }
    }
    #undef LOAD_CHUNK

    // ---- epilogue phase 1: exp in-register, accumulate row sums ----
    const int tg = lane & 3, gr = lane >> 2;
    #pragma unroll
    for (int mi = 0; mi < 4; ++mi) {
        const int row = m0 + wm + mi * 16 + gr;
        float rs0 = 0.f, rs1 = 0.f;
        #pragma unroll
        for (int ni = 0; ni < 8; ++ni) {
            const int cl = wn + ni * 8 + tg * 2;
            const float b0 = sbias[cl], b1 = sbias[cl + 1];
            float e00 = __expf((acc[mi][ni][0] + b0) * SCALE);
            float e01 = __expf((acc[mi][ni][1] + b1) * SCALE);
            float e10 = __expf((acc[mi][ni][2] + b0) * SCALE);
            float e11 = __expf((acc[mi][ni][3] + b1) * SCALE);
            acc[mi][ni][0] = e00; acc[mi][ni][1] = e01;
            acc[mi][ni][2] = e10; acc[mi][ni][3] = e11;
            rs0 += e00 + e01;
            rs1 += e10 + e11;
        }
        rs0 += __shfl_xor_sync(0xffffffffu, rs0, 1);
        rs0 += __shfl_xor_sync(0xffffffffu, rs0, 2);
        rs1 += __shfl_xor_sync(0xffffffffu, rs1, 1);
        rs1 += __shfl_xor_sync(0xffffffffu, rs1, 2);
        if (tg == 0) {
            atomicAdd(&g_rsum[row], rs0);
            atomicAdd(&g_rsum[row + 8], rs1);
        }
    }
    __threadfence();
    __syncthreads();

    // ---- cohort barrier: wait for all 125 N-tiles of this M-block ----
    if (tid == 0) {
        atomicAdd(&g_cnt[blockIdx.y], 1u);
        while (*(volatile unsigned*)&g_cnt[blockIdx.y] < 125u) __nanosleep(64);
        __threadfence();
    }
    __syncthreads();

    // ---- epilogue phase 2: scale by 1/rsum, store final values ----
    #pragma unroll
    for (int mi = 0; mi < 4; ++mi) {
        const int row = m0 + wm + mi * 16 + gr;
        const float inv0 = 1.0f / __ldcg(&g_rsum[row]);
        const float inv1 = 1.0f / __ldcg(&g_rsum[row + 8]);
        #pragma unroll
        for (int ni = 0; ni < 8; ++ni) {
            const int cl = wn + ni * 8 + tg * 2;
            float2 v0 = {acc[mi][ni][0] * inv0, acc[mi][ni][1] * inv0};
            float2 v1 = {acc[mi][ni][2] * inv1, acc[mi][ni][3] * inv1};
            *(float2*)(out + (size_t)row * NV + n0 + cl)       = v0;
            *(float2*)(out + (size_t)(row + 8) * NV + n0 + cl) = v1;
        }
    }
}

// ---------------------------------------------------------------------------
// Kernel D: scatter normalized copy probs (rsum is final after GEMM)
// ---------------------------------------------------------------------------
__global__ __launch_bounds__(320)
void scatter_kernel(const int* __restrict__ context, const int* __restrict__ tp,
                    const int* __restrict__ action, const int* __restrict__ loc2glo,
                    float* __restrict__ out)
{
    const int t = threadIdx.x;   // 0..319
    for (int r = 0; r < 4; ++r) {
        const int row = blockIdx.x * 4 + r;
        const int b   = row >> 7;
        const float inv = 1.0f / __ldcg(&g_rsum[row]);
        const float e = g_copye[row][t] * inv;

        int idx;
        if (t < CTXL)            idx = context[b * CTXL + t];
        else if (t < CTXL + STN) idx = loc2glo[tp[b * STN + (t - CTXL)]];
        else                     idx = loc2glo[action[b * STN + (t - CTXL - STN)]];
        atomicAdd(out + (size_t)row * NV + idx, e);
    }
}

// ---------------------------------------------------------------------------
extern "C" void kernel_launch(void* const* d_in, const int* in_sizes, int n_in,
                              void* d_out, int out_size)
{
    const float* dec     = (const float*)d_in[0];  // (8,128,512)
    const float* src     = (const float*)d_in[1];  // (8,320,512)
    const float* W       = (const float*)d_in[2];  // (512,32000)
    const float* bgen    = (const float*)d_in[3];  // (32000,)
    const int*   mask    = (const int*)d_in[4];    // (8,1,320)
    const int*   context = (const int*)d_in[5];    // (8,256)
    const int*   tp      = (const int*)d_in[6];    // (8,32)
    const int*   action  = (const int*)d_in[7];    // (8,32)
    const int*   loc2glo = (const int*)d_in[8];    // (4096,)
    float*       out     = (float*)d_out;          // (8,128,32000)

    cudaFuncSetAttribute(gemm_kernel,
                         cudaFuncAttributeMaxDynamicSharedMemorySize, DYN_BYTES);

    prep_kernel<<<CP_BLK + CV_BLK, 256>>>(W, dec, src);
    copysum_kernel<<<NROWS / 4, 320>>>(mask);
    gemm_kernel<<<dim3(125, 8), 256, DYN_BYTES>>>(bgen, out);
    scatter_kernel<<<NROWS / 4, 320>>>(context, tp, action, loc2glo, out);
}

// round 12
// speedup vs baseline: 1.1089x; 1.1089x over previous
#include <cuda_runtime.h>
#include <cuda_bf16.h>
#include <stdint.h>

#define NROWS 1024
#define NV    32000
#define LSRC  320
#define CTXL  256
#define STN   32
#define HDIM  512
#define SCALE 0.04419417382415922f   // 1/sqrt(512)

__device__ __nv_bfloat16 g_Wbf[(size_t)HDIM * NV];    // W bf16, [k][n]
__device__ __nv_bfloat16 g_Abf[(size_t)NROWS * HDIM]; // dec bf16, [m][k]
__device__ float g_copy4[4][NROWS][LSRC];             // split-K copy logit partials
__device__ float g_rsum[NROWS];                       // gen-side row sums (atomic)

// ---------------------------------------------------------------------------
// helpers (mma.sync only — tcgen05 rejected by harness's compute_103 stage)
// ---------------------------------------------------------------------------
__device__ __forceinline__ uint32_t smem_u32(const void* p) {
    return (uint32_t)__cvta_generic_to_shared(p);
}
__device__ __forceinline__ void cp_async16(uint32_t dst, const void* src) {
    asm volatile("cp.async.cg.shared.global [%0], [%1], 16;\n" :: "r"(dst), "l"(src));
}
__device__ __forceinline__ void cp_commit() {
    asm volatile("cp.async.commit_group;\n");
}
template <int N> __device__ __forceinline__ void cp_wait() {
    asm volatile("cp.async.wait_group %0;\n" :: "n"(N));
}
#define SWZ128(o) ((o) ^ (((o) >> 3) & 0x70))

__device__ __forceinline__ void ldsm_x4(uint32_t* r, uint32_t a) {
    asm volatile("ldmatrix.sync.aligned.m8n8.x4.shared.b16 {%0,%1,%2,%3}, [%4];\n"
                 : "=r"(r[0]), "=r"(r[1]), "=r"(r[2]), "=r"(r[3]) : "r"(a));
}
__device__ __forceinline__ void ldsm_x4_t(uint32_t* r, uint32_t a) {
    asm volatile("ldmatrix.sync.aligned.m8n8.x4.trans.shared.b16 {%0,%1,%2,%3}, [%4];\n"
                 : "=r"(r[0]), "=r"(r[1]), "=r"(r[2]), "=r"(r[3]) : "r"(a));
}
__device__ __forceinline__ void mma16816(float* c, const uint32_t* a, const uint32_t* b) {
    asm volatile(
        "mma.sync.aligned.m16n8k16.row.col.f32.bf16.bf16.f32 "
        "{%0,%1,%2,%3}, {%4,%5,%6,%7}, {%8,%9}, {%0,%1,%2,%3};\n"
        : "+f"(c[0]), "+f"(c[1]), "+f"(c[2]), "+f"(c[3])
        : "r"(a[0]), "r"(a[1]), "r"(a[2]), "r"(a[3]),
          "r"(b[0]), "r"(b[1]));
}

// ---------------------------------------------------------------------------
// Kernel A: copy-logit split-K partials + W/dec bf16 convert + rsum zero
// ---------------------------------------------------------------------------
#define CP_BLK 640
#define NW4 ((HDIM * (size_t)NV) / 4)
#define NA4 ((NROWS * (size_t)HDIM) / 4)
#define CV_BLK ((unsigned)((NW4 + NA4 + 255) / 256))

__global__ __launch_bounds__(256)
void prep_kernel(const float* __restrict__ W, const float* __restrict__ dec,
                 const float* __restrict__ src)
{
    const int bid = blockIdx.x;
    const int tid = threadIdx.x;

    if (bid < CP_BLK) {
        // ---- copy-logit split-K partial: tile 32 l x 64 s x 128 k ----
        const int kq = bid & 3;
        const int rest = bid >> 2;
        const int st = rest % 5;
        const int r2 = rest / 5;
        const int lt = r2 & 3, b = r2 >> 2;

        __shared__ float sA[2][32][17];
        __shared__ float sB[2][64][17];

        const float* Ag = dec + (size_t)(b * 128 + lt * 32) * HDIM + kq * 128;
        const float* Bg = src + (size_t)(b * LSRC + st * 64) * HDIM + kq * 128;

        const int ar = tid >> 3;
        const int ac = (tid & 7) * 2;

        float2 ra = *(const float2*)(Ag + (size_t)ar * HDIM + ac);
        float2 rb0 = *(const float2*)(Bg + (size_t)ar * HDIM + ac);
        float2 rb1 = *(const float2*)(Bg + (size_t)(ar + 32) * HDIM + ac);
        sA[0][ar][ac] = ra.x;  sA[0][ar][ac + 1] = ra.y;
        sB[0][ar][ac] = rb0.x; sB[0][ar][ac + 1] = rb0.y;
        sB[0][ar + 32][ac] = rb1.x; sB[0][ar + 32][ac + 1] = rb1.y;
        __syncthreads();

        const int ty = tid >> 5;
        const int tx = tid & 31;
        float acc[4][2] = {};

        for (int kt = 0; kt < 8; ++kt) {
            const int buf = kt & 1;
            if (kt < 7) {
                const int k0 = (kt + 1) * 16;
                ra  = *(const float2*)(Ag + (size_t)ar * HDIM + k0 + ac);
                rb0 = *(const float2*)(Bg + (size_t)ar * HDIM + k0 + ac);
                rb1 = *(const float2*)(Bg + (size_t)(ar + 32) * HDIM + k0 + ac);
            }
            #pragma unroll
            for (int k = 0; k < 16; ++k) {
                float a0 = sA[buf][ty * 4 + 0][k];
                float a1 = sA[buf][ty * 4 + 1][k];
                float a2 = sA[buf][ty * 4 + 2][k];
                float a3 = sA[buf][ty * 4 + 3][k];
                float b0 = sB[buf][tx * 2 + 0][k];
                float b1 = sB[buf][tx * 2 + 1][k];
                acc[0][0] += a0 * b0; acc[0][1] += a0 * b1;
                acc[1][0] += a1 * b0; acc[1][1] += a1 * b1;
                acc[2][0] += a2 * b0; acc[2][1] += a2 * b1;
                acc[3][0] += a3 * b0; acc[3][1] += a3 * b1;
            }
            if (kt < 7) {
                const int nb = 1 - buf;
                sA[nb][ar][ac] = ra.x;  sA[nb][ar][ac + 1] = ra.y;
                sB[nb][ar][ac] = rb0.x; sB[nb][ar][ac + 1] = rb0.y;
                sB[nb][ar + 32][ac] = rb1.x; sB[nb][ar + 32][ac + 1] = rb1.y;
            }
            __syncthreads();
        }

        #pragma unroll
        for (int i = 0; i < 4; ++i) {
            const int row = b * 128 + lt * 32 + ty * 4 + i;
            #pragma unroll
            for (int j = 0; j < 2; ++j)
                g_copy4[kq][row][st * 64 + tx * 2 + j] = acc[i][j];
        }
    } else {
        // ---- flat bf16 convert + rsum zero ----
        const size_t gid = (size_t)(bid - CP_BLK) * 256 + tid;
        if (gid < NROWS) g_rsum[gid] = 0.f;
        if (gid < NW4) {
            float4 v = ((const float4*)W)[gid];
            __nv_bfloat162 p0 = __floats2bfloat162_rn(v.x, v.y);
            __nv_bfloat162 p1 = __floats2bfloat162_rn(v.z, v.w);
            uint2 o = {*(uint32_t*)&p0, *(uint32_t*)&p1};
            ((uint2*)g_Wbf)[gid] = o;
        } else if (gid < NW4 + NA4) {
            const size_t i = gid - NW4;
            float4 v = ((const float4*)dec)[i];
            __nv_bfloat162 p0 = __floats2bfloat162_rn(v.x, v.y);
            __nv_bfloat162 p1 = __floats2bfloat162_rn(v.z, v.w);
            uint2 o = {*(uint32_t*)&p0, *(uint32_t*)&p1};
            ((uint2*)g_Abf)[i] = o;
        }
    }
}

// ---------------------------------------------------------------------------
// Kernel B: mma.sync gen GEMM fused with exp + row-sum (R8 config — best).
//   BM=128 BN=128 BK=64, 256 thr (8 warps 2x4, warp tile 64x32),
//   3-stage cp.async pipeline, 2 CTAs/SM. Stores unnormalized exps.
// ---------------------------------------------------------------------------
#define KC 64
#define SA_BYTES 16384
#define SB_BYTES (64 * 272)
#define STAGE_BYTES (SA_BYTES + SB_BYTES)   // 33792
#define DYN_BYTES (3 * STAGE_BYTES + 1024)  // 102400

__global__ __launch_bounds__(256, 2)
void gemm_kernel(const float* __restrict__ bias, float* __restrict__ out)
{
    extern __shared__ char dyn[];
    __shared__ float sbias[128];

    const int tid  = threadIdx.x;
    const int warp = tid >> 5, lane = tid & 31;
    const int m0 = blockIdx.x * 128;
    const int n0 = blockIdx.y * 128;
    const int wm = (warp >> 2) * 64;
    const int wn = (warp & 3) * 32;
    const uint32_t base = (smem_u32(dyn) + 1023) & ~1023u;

    if (tid < 128) sbias[tid] = bias[n0 + tid];

    const int a_r  = tid >> 1;
    const int a_cb = (tid & 1) * 64;
    const int b_k  = tid >> 2;
    const int b_cb = (tid & 3) * 64;

    #define LOAD_CHUNK(c) do {                                                   \
        const int _s = (c) % 3;                                                  \
        const uint32_t _sa = base + _s * STAGE_BYTES;                            \
        const uint32_t _sb = _sa + SA_BYTES;                                     \
        _Pragma("unroll")                                                        \
        for (int _i = 0; _i < 4; ++_i) {                                         \
            const uint32_t _ao = (uint32_t)(a_r * 128 + a_cb + _i * 16);         \
            cp_async16(_sa + SWZ128(_ao),                                        \
                       g_Abf + (size_t)(m0 + a_r) * HDIM + (c) * KC              \
                             + (a_cb >> 1) + _i * 8);                            \
            cp_async16(_sb + b_k * 272 + b_cb + _i * 16,                         \
                       g_Wbf + (size_t)((c) * KC + b_k) * NV + n0               \
                             + (b_cb >> 1) + _i * 8);                            \
        }                                                                        \
    } while (0)

    LOAD_CHUNK(0); cp_commit();
    LOAD_CHUNK(1); cp_commit();

    float acc[4][4][4];
    #pragma unroll
    for (int i = 0; i < 4; ++i)
        #pragma unroll
        for (int j = 0; j < 4; ++j)
            #pragma unroll
            for (int q = 0; q < 4; ++q) acc[i][j][q] = 0.f;

    const int KT = HDIM / KC;   // 8
    for (int kt = 0; kt < KT; ++kt) {
        if (kt < KT - 2) cp_wait<1>(); else cp_wait<0>();
        __syncthreads();

        if (kt + 2 < KT) LOAD_CHUNK(kt + 2);
        cp_commit();

        const int st = kt % 3;
        const uint32_t aS = base + st * STAGE_BYTES;
        const uint32_t bS = aS + SA_BYTES;

        #pragma unroll
        for (int kk = 0; kk < 4; ++kk) {
            uint32_t af[4][4], bfr[4][2];
            #pragma unroll
            for (int mi = 0; mi < 4; ++mi) {
                const uint32_t off = (uint32_t)((wm + mi * 16 + (lane & 15)) * 128
                                                + kk * 32 + (lane >> 4) * 16);
                ldsm_x4(af[mi], aS + SWZ128(off));
            }
            #pragma unroll
            for (int g = 0; g < 2; ++g) {
                uint32_t r[4];
                const uint32_t addr = bS + (kk * 16 + (lane & 15)) * 272
                                         + wn * 2 + g * 32 + (lane >> 4) * 16;
                ldsm_x4_t(r, addr);
                bfr[g * 2][0] = r[0];     bfr[g * 2][1] = r[1];
                bfr[g * 2 + 1][0] = r[2]; bfr[g * 2 + 1][1] = r[3];
            }
            #pragma unroll
            for (int mi = 0; mi < 4; ++mi)
                #pragma unroll
                for (int ni = 0; ni < 4; ++ni)
                    mma16816(acc[mi][ni], af[mi], bfr[ni]);
        }
    }
    #undef LOAD_CHUNK

    // epilogue: exp((acc + bias) * SCALE) -> out ; partial row sums
    const int tg = lane & 3, gr = lane >> 2;
    #pragma unroll
    for (int mi = 0; mi < 4; ++mi) {
        const int row = m0 + wm + mi * 16 + gr;
        float rs0 = 0.f, rs1 = 0.f;
        #pragma unroll
        for (int ni = 0; ni < 4; ++ni) {
            const int cl = wn + ni * 8 + tg * 2;
            const float b0 = sbias[cl], b1 = sbias[cl + 1];
            float e00 = __expf((acc[mi][ni][0] + b0) * SCALE);
            float e01 = __expf((acc[mi][ni][1] + b1) * SCALE);
            float e10 = __expf((acc[mi][ni][2] + b0) * SCALE);
            float e11 = __expf((acc[mi][ni][3] + b1) * SCALE);
            rs0 += e00 + e01;
            rs1 += e10 + e11;
            float2 v0 = {e00, e01}, v1 = {e10, e11};
            *(float2*)(out + (size_t)row * NV + n0 + cl)       = v0;
            *(float2*)(out + (size_t)(row + 8) * NV + n0 + cl) = v1;
        }
        rs0 += __shfl_xor_sync(0xffffffffu, rs0, 1);
        rs0 += __shfl_xor_sync(0xffffffffu, rs0, 2);
        rs1 += __shfl_xor_sync(0xffffffffu, rs1, 1);
        rs1 += __shfl_xor_sync(0xffffffffu, rs1, 2);
        if (tg == 0) {
            atomicAdd(&g_rsum[row], rs0);
            atomicAdd(&g_rsum[row + 8], rs1);
        }
    }
}

// ---------------------------------------------------------------------------
// Kernel C (fused): per-row normalize + scatter.
//   One block per row, 512 threads. Computes the copy-exp sum locally from
//   the split-K partials (no atomics), adds to the gen sum, normalizes the
//   32000 gen exps in place, then scatters normalized copy probs.
// ---------------------------------------------------------------------------
__global__ __launch_bounds__(512)
void norm_scatter_kernel(const int* __restrict__ mask, const int* __restrict__ context,
                         const int* __restrict__ tp, const int* __restrict__ action,
                         const int* __restrict__ loc2glo, float* __restrict__ out)
{
    const int row = blockIdx.x;
    const int t   = threadIdx.x;   // 0..511
    const int b   = row >> 7;

    __shared__ float sred[16];
    __shared__ float sinv;
    __shared__ float se[LSRC];

    // copy-exp + local reduction (threads 0..319)
    float e = 0.f;
    if (t < LSRC) {
        float dot = g_copy4[0][row][t] + g_copy4[1][row][t]
                  + g_copy4[2][row][t] + g_copy4[3][row][t];
        e = (mask[b * LSRC + t] == 0) ? 0.f : __expf(dot * SCALE);
        se[t] = e;
    }
    float w = e;
    #pragma unroll
    for (int off = 16; off > 0; off >>= 1)
        w += __shfl_xor_sync(0xffffffffu, w, off);
    if ((t & 31) == 0) sred[t >> 5] = w;
    __syncthreads();
    if (t == 0) {
        float s = 0.f;
        #pragma unroll
        for (int i = 0; i < 16; ++i) s += sred[i];
        sinv = 1.0f / (s + g_rsum[row]);
    }
    __syncthreads();
    const float inv = sinv;

    // normalize the 32000 gen exps in place
    float4* o4 = (float4*)(out + (size_t)row * NV);
    #pragma unroll 4
    for (int i = t; i < NV / 4; i += 512) {
        float4 v = o4[i];
        v.x *= inv; v.y *= inv; v.z *= inv; v.w *= inv;
        o4[i] = v;
    }
    __syncthreads();

    // scatter normalized copy probs
    if (t < LSRC) {
        int idx;
        if (t < CTXL)            idx = context[b * CTXL + t];
        else if (t < CTXL + STN) idx = loc2glo[tp[b * STN + (t - CTXL)]];
        else                     idx = loc2glo[action[b * STN + (t - CTXL - STN)]];
        atomicAdd(out + (size_t)row * NV + idx, se[t] * inv);
    }
}

// ---------------------------------------------------------------------------
extern "C" void kernel_launch(void* const* d_in, const int* in_sizes, int n_in,
                              void* d_out, int out_size)
{
    const float* dec     = (const float*)d_in[0];  // (8,128,512)
    const float* src     = (const float*)d_in[1];  // (8,320,512)
    const float* W       = (const float*)d_in[2];  // (512,32000)
    const float* bgen    = (const float*)d_in[3];  // (32000,)
    const int*   mask    = (const int*)d_in[4];    // (8,1,320)
    const int*   context = (const int*)d_in[5];    // (8,256)
    const int*   tp      = (const int*)d_in[6];    // (8,32)
    const int*   action  = (const int*)d_in[7];    // (8,32)
    const int*   loc2glo = (const int*)d_in[8];    // (4096,)
    float*       out     = (float*)d_out;          // (8,128,32000)

    cudaFuncSetAttribute(gemm_kernel,
                         cudaFuncAttributeMaxDynamicSharedMemorySize, DYN_BYTES);

    prep_kernel<<<CP_BLK + CV_BLK, 256>>>(W, dec, src);
    gemm_kernel<<<dim3(8, 250), 256, DYN_BYTES>>>(bgen, out);
    norm_scatter_kernel<<<NROWS, 512>>>(mask, context, tp, action, loc2glo, out);
}

// round 13
// speedup vs baseline: 1.1215x; 1.0113x over previous
#include <cuda_runtime.h>
#include <cuda_bf16.h>
#include <stdint.h>

#define NROWS 1024
#define NV    32000
#define LSRC  320
#define CTXL  256
#define STN   32
#define HDIM  512
#define SCALE 0.04419417382415922f   // 1/sqrt(512)

__device__ __nv_bfloat16 g_Wbf[(size_t)HDIM * NV];    // W bf16, [k][n]
__device__ __nv_bfloat16 g_Abf[(size_t)NROWS * HDIM]; // dec bf16, [m][k]
__device__ float g_copy4[4][NROWS][LSRC];             // split-K copy logit partials
__device__ float g_rsum[NROWS];                       // gen-side row sums (atomic)

// ---------------------------------------------------------------------------
// helpers (mma.sync only — tcgen05 rejected by harness's compute_103 stage)
// ---------------------------------------------------------------------------
__device__ __forceinline__ uint32_t smem_u32(const void* p) {
    return (uint32_t)__cvta_generic_to_shared(p);
}
__device__ __forceinline__ void cp_async16(uint32_t dst, const void* src) {
    asm volatile("cp.async.cg.shared.global [%0], [%1], 16;\n" :: "r"(dst), "l"(src));
}
__device__ __forceinline__ void cp_commit() {
    asm volatile("cp.async.commit_group;\n");
}
template <int N> __device__ __forceinline__ void cp_wait() {
    asm volatile("cp.async.wait_group %0;\n" :: "n"(N));
}
#define SWZ128(o) ((o) ^ (((o) >> 3) & 0x70))

__device__ __forceinline__ void ldsm_x4(uint32_t* r, uint32_t a) {
    asm volatile("ldmatrix.sync.aligned.m8n8.x4.shared.b16 {%0,%1,%2,%3}, [%4];\n"
                 : "=r"(r[0]), "=r"(r[1]), "=r"(r[2]), "=r"(r[3]) : "r"(a));
}
__device__ __forceinline__ void ldsm_x4_t(uint32_t* r, uint32_t a) {
    asm volatile("ldmatrix.sync.aligned.m8n8.x4.trans.shared.b16 {%0,%1,%2,%3}, [%4];\n"
                 : "=r"(r[0]), "=r"(r[1]), "=r"(r[2]), "=r"(r[3]) : "r"(a));
}
__device__ __forceinline__ void mma16816(float* c, const uint32_t* a, const uint32_t* b) {
    asm volatile(
        "mma.sync.aligned.m16n8k16.row.col.f32.bf16.bf16.f32 "
        "{%0,%1,%2,%3}, {%4,%5,%6,%7}, {%8,%9}, {%0,%1,%2,%3};\n"
        : "+f"(c[0]), "+f"(c[1]), "+f"(c[2]), "+f"(c[3])
        : "r"(a[0]), "r"(a[1]), "r"(a[2]), "r"(a[3]),
          "r"(b[0]), "r"(b[1]));
}

// ---------------------------------------------------------------------------
// Kernel A1: copy-logit split-K partials (640 blocks, register-heavy)
// ---------------------------------------------------------------------------
#define CP_BLK 640

__global__ __launch_bounds__(256)
void copy_kernel(const float* __restrict__ dec, const float* __restrict__ src)
{
    const int bid = blockIdx.x;
    const int tid = threadIdx.x;

    const int kq = bid & 3;
    const int rest = bid >> 2;
    const int st = rest % 5;
    const int r2 = rest / 5;
    const int lt = r2 & 3, b = r2 >> 2;

    __shared__ float sA[2][32][17];
    __shared__ float sB[2][64][17];

    const float* Ag = dec + (size_t)(b * 128 + lt * 32) * HDIM + kq * 128;
    const float* Bg = src + (size_t)(b * LSRC + st * 64) * HDIM + kq * 128;

    const int ar = tid >> 3;
    const int ac = (tid & 7) * 2;

    float2 ra = *(const float2*)(Ag + (size_t)ar * HDIM + ac);
    float2 rb0 = *(const float2*)(Bg + (size_t)ar * HDIM + ac);
    float2 rb1 = *(const float2*)(Bg + (size_t)(ar + 32) * HDIM + ac);
    sA[0][ar][ac] = ra.x;  sA[0][ar][ac + 1] = ra.y;
    sB[0][ar][ac] = rb0.x; sB[0][ar][ac + 1] = rb0.y;
    sB[0][ar + 32][ac] = rb1.x; sB[0][ar + 32][ac + 1] = rb1.y;
    __syncthreads();

    const int ty = tid >> 5;
    const int tx = tid & 31;
    float acc[4][2] = {};

    for (int kt = 0; kt < 8; ++kt) {
        const int buf = kt & 1;
        if (kt < 7) {
            const int k0 = (kt + 1) * 16;
            ra  = *(const float2*)(Ag + (size_t)ar * HDIM + k0 + ac);
            rb0 = *(const float2*)(Bg + (size_t)ar * HDIM + k0 + ac);
            rb1 = *(const float2*)(Bg + (size_t)(ar + 32) * HDIM + k0 + ac);
        }
        #pragma unroll
        for (int k = 0; k < 16; ++k) {
            float a0 = sA[buf][ty * 4 + 0][k];
            float a1 = sA[buf][ty * 4 + 1][k];
            float a2 = sA[buf][ty * 4 + 2][k];
            float a3 = sA[buf][ty * 4 + 3][k];
            float b0 = sB[buf][tx * 2 + 0][k];
            float b1 = sB[buf][tx * 2 + 1][k];
            acc[0][0] += a0 * b0; acc[0][1] += a0 * b1;
            acc[1][0] += a1 * b0; acc[1][1] += a1 * b1;
            acc[2][0] += a2 * b0; acc[2][1] += a2 * b1;
            acc[3][0] += a3 * b0; acc[3][1] += a3 * b1;
        }
        if (kt < 7) {
            const int nb = 1 - buf;
            sA[nb][ar][ac] = ra.x;  sA[nb][ar][ac + 1] = ra.y;
            sB[nb][ar][ac] = rb0.x; sB[nb][ar][ac + 1] = rb0.y;
            sB[nb][ar + 32][ac] = rb1.x; sB[nb][ar + 32][ac + 1] = rb1.y;
        }
        __syncthreads();
    }

    #pragma unroll
    for (int i = 0; i < 4; ++i) {
        const int row = b * 128 + lt * 32 + ty * 4 + i;
        #pragma unroll
        for (int j = 0; j < 2; ++j)
            g_copy4[kq][row][st * 64 + tx * 2 + j] = acc[i][j];
    }
}

// ---------------------------------------------------------------------------
// Kernel A2: lean streaming convert (W + dec -> bf16) + rsum zero.
//   Low register count -> full occupancy -> DRAM-rate streaming.
// ---------------------------------------------------------------------------
#define NW4 ((HDIM * (size_t)NV) / 4)
#define NA4 ((NROWS * (size_t)HDIM) / 4)
#define CV_BLK ((unsigned)((NW4 + NA4 + 255) / 256))

__global__ __launch_bounds__(256)
void convert_kernel(const float* __restrict__ W, const float* __restrict__ dec)
{
    const size_t gid = (size_t)blockIdx.x * 256 + threadIdx.x;
    if (gid < NROWS) g_rsum[gid] = 0.f;
    if (gid < NW4) {
        float4 v = ((const float4*)W)[gid];
        __nv_bfloat162 p0 = __floats2bfloat162_rn(v.x, v.y);
        __nv_bfloat162 p1 = __floats2bfloat162_rn(v.z, v.w);
        uint2 o = {*(uint32_t*)&p0, *(uint32_t*)&p1};
        ((uint2*)g_Wbf)[gid] = o;
    } else if (gid < NW4 + NA4) {
        const size_t i = gid - NW4;
        float4 v = ((const float4*)dec)[i];
        __nv_bfloat162 p0 = __floats2bfloat162_rn(v.x, v.y);
        __nv_bfloat162 p1 = __floats2bfloat162_rn(v.z, v.w);
        uint2 o = {*(uint32_t*)&p0, *(uint32_t*)&p1};
        ((uint2*)g_Abf)[i] = o;
    }
}

// ---------------------------------------------------------------------------
// Kernel B: mma.sync gen GEMM fused with exp + row-sum (R8 config — best).
//   BM=128 BN=128 BK=64, 256 thr (8 warps 2x4, warp tile 64x32),
//   3-stage cp.async pipeline, 2 CTAs/SM. Stores unnormalized exps.
// ---------------------------------------------------------------------------
#define KC 64
#define SA_BYTES 16384
#define SB_BYTES (64 * 272)
#define STAGE_BYTES (SA_BYTES + SB_BYTES)   // 33792
#define DYN_BYTES (3 * STAGE_BYTES + 1024)  // 102400

__global__ __launch_bounds__(256, 2)
void gemm_kernel(const float* __restrict__ bias, float* __restrict__ out)
{
    extern __shared__ char dyn[];
    __shared__ float sbias[128];

    const int tid  = threadIdx.x;
    const int warp = tid >> 5, lane = tid & 31;
    const int m0 = blockIdx.x * 128;
    const int n0 = blockIdx.y * 128;
    const int wm = (warp >> 2) * 64;
    const int wn = (warp & 3) * 32;
    const uint32_t base = (smem_u32(dyn) + 1023) & ~1023u;

    if (tid < 128) sbias[tid] = bias[n0 + tid];

    const int a_r  = tid >> 1;
    const int a_cb = (tid & 1) * 64;
    const int b_k  = tid >> 2;
    const int b_cb = (tid & 3) * 64;

    #define LOAD_CHUNK(c) do {                                                   \
        const int _s = (c) % 3;                                                  \
        const uint32_t _sa = base + _s * STAGE_BYTES;                            \
        const uint32_t _sb = _sa + SA_BYTES;                                     \
        _Pragma("unroll")                                                        \
        for (int _i = 0; _i < 4; ++_i) {                                         \
            const uint32_t _ao = (uint32_t)(a_r * 128 + a_cb + _i * 16);         \
            cp_async16(_sa + SWZ128(_ao),                                        \
                       g_Abf + (size_t)(m0 + a_r) * HDIM + (c) * KC              \
                             + (a_cb >> 1) + _i * 8);                            \
            cp_async16(_sb + b_k * 272 + b_cb + _i * 16,                         \
                       g_Wbf + (size_t)((c) * KC + b_k) * NV + n0               \
                             + (b_cb >> 1) + _i * 8);                            \
        }                                                                        \
    } while (0)

    LOAD_CHUNK(0); cp_commit();
    LOAD_CHUNK(1); cp_commit();

    float acc[4][4][4];
    #pragma unroll
    for (int i = 0; i < 4; ++i)
        #pragma unroll
        for (int j = 0; j < 4; ++j)
            #pragma unroll
            for (int q = 0; q < 4; ++q) acc[i][j][q] = 0.f;

    const int KT = HDIM / KC;   // 8
    for (int kt = 0; kt < KT; ++kt) {
        if (kt < KT - 2) cp_wait<1>(); else cp_wait<0>();
        __syncthreads();

        if (kt + 2 < KT) LOAD_CHUNK(kt + 2);
        cp_commit();

        const int st = kt % 3;
        const uint32_t aS = base + st * STAGE_BYTES;
        const uint32_t bS = aS + SA_BYTES;

        #pragma unroll
        for (int kk = 0; kk < 4; ++kk) {
            uint32_t af[4][4], bfr[4][2];
            #pragma unroll
            for (int mi = 0; mi < 4; ++mi) {
                const uint32_t off = (uint32_t)((wm + mi * 16 + (lane & 15)) * 128
                                                + kk * 32 + (lane >> 4) * 16);
                ldsm_x4(af[mi], aS + SWZ128(off));
            }
            #pragma unroll
            for (int g = 0; g < 2; ++g) {
                uint32_t r[4];
                const uint32_t addr = bS + (kk * 16 + (lane & 15)) * 272
                                         + wn * 2 + g * 32 + (lane >> 4) * 16;
                ldsm_x4_t(r, addr);
                bfr[g * 2][0] = r[0];     bfr[g * 2][1] = r[1];
                bfr[g * 2 + 1][0] = r[2]; bfr[g * 2 + 1][1] = r[3];
            }
            #pragma unroll
            for (int mi = 0; mi < 4; ++mi)
                #pragma unroll
                for (int ni = 0; ni < 4; ++ni)
                    mma16816(acc[mi][ni], af[mi], bfr[ni]);
        }
    }
    #undef LOAD_CHUNK

    // epilogue: exp((acc + bias) * SCALE) -> out ; partial row sums
    const int tg = lane & 3, gr = lane >> 2;
    #pragma unroll
    for (int mi = 0; mi < 4; ++mi) {
        const int row = m0 + wm + mi * 16 + gr;
        float rs0 = 0.f, rs1 = 0.f;
        #pragma unroll
        for (int ni = 0; ni < 4; ++ni) {
            const int cl = wn + ni * 8 + tg * 2;
            const float b0 = sbias[cl], b1 = sbias[cl + 1];
            float e00 = __expf((acc[mi][ni][0] + b0) * SCALE);
            float e01 = __expf((acc[mi][ni][1] + b1) * SCALE);
            float e10 = __expf((acc[mi][ni][2] + b0) * SCALE);
            float e11 = __expf((acc[mi][ni][3] + b1) * SCALE);
            rs0 += e00 + e01;
            rs1 += e10 + e11;
            float2 v0 = {e00, e01}, v1 = {e10, e11};
            *(float2*)(out + (size_t)row * NV + n0 + cl)       = v0;
            *(float2*)(out + (size_t)(row + 8) * NV + n0 + cl) = v1;
        }
        rs0 += __shfl_xor_sync(0xffffffffu, rs0, 1);
        rs0 += __shfl_xor_sync(0xffffffffu, rs0, 2);
        rs1 += __shfl_xor_sync(0xffffffffu, rs1, 1);
        rs1 += __shfl_xor_sync(0xffffffffu, rs1, 2);
        if (tg == 0) {
            atomicAdd(&g_rsum[row], rs0);
            atomicAdd(&g_rsum[row + 8], rs1);
        }
    }
}

// ---------------------------------------------------------------------------
// Kernel C (fused): per-row normalize + scatter.
// ---------------------------------------------------------------------------
__global__ __launch_bounds__(512)
void norm_scatter_kernel(const int* __restrict__ mask, const int* __restrict__ context,
                         const int* __restrict__ tp, const int* __restrict__ action,
                         const int* __restrict__ loc2glo, float* __restrict__ out)
{
    const int row = blockIdx.x;
    const int t   = threadIdx.x;   // 0..511
    const int b   = row >> 7;

    __shared__ float sred[16];
    __shared__ float sinv;
    __shared__ float se[LSRC];

    float e = 0.f;
    if (t < LSRC) {
        float dot = g_copy4[0][row][t] + g_copy4[1][row][t]
                  + g_copy4[2][row][t] + g_copy4[3][row][t];
        e = (mask[b * LSRC + t] == 0) ? 0.f : __expf(dot * SCALE);
        se[t] = e;
    }
    float w = e;
    #pragma unroll
    for (int off = 16; off > 0; off >>= 1)
        w += __shfl_xor_sync(0xffffffffu, w, off);
    if ((t & 31) == 0) sred[t >> 5] = w;
    __syncthreads();
    if (t == 0) {
        float s = 0.f;
        #pragma unroll
        for (int i = 0; i < 16; ++i) s += sred[i];
        sinv = 1.0f / (s + g_rsum[row]);
    }
    __syncthreads();
    const float inv = sinv;

    float4* o4 = (float4*)(out + (size_t)row * NV);
    #pragma unroll 4
    for (int i = t; i < NV / 4; i += 512) {
        float4 v = o4[i];
        v.x *= inv; v.y *= inv; v.z *= inv; v.w *= inv;
        o4[i] = v;
    }
    __syncthreads();

    if (t < LSRC) {
        int idx;
        if (t < CTXL)            idx = context[b * CTXL + t];
        else if (t < CTXL + STN) idx = loc2glo[tp[b * STN + (t - CTXL)]];
        else                     idx = loc2glo[action[b * STN + (t - CTXL - STN)]];
        atomicAdd(out + (size_t)row * NV + idx, se[t] * inv);
    }
}

// ---------------------------------------------------------------------------
extern "C" void kernel_launch(void* const* d_in, const int* in_sizes, int n_in,
                              void* d_out, int out_size)
{
    const float* dec     = (const float*)d_in[0];  // (8,128,512)
    const float* src     = (const float*)d_in[1];  // (8,320,512)
    const float* W       = (const float*)d_in[2];  // (512,32000)
    const float* bgen    = (const float*)d_in[3];  // (32000,)
    const int*   mask    = (const int*)d_in[4];    // (8,1,320)
    const int*   context = (const int*)d_in[5];    // (8,256)
    const int*   tp      = (const int*)d_in[6];    // (8,32)
    const int*   action  = (const int*)d_in[7];    // (8,32)
    const int*   loc2glo = (const int*)d_in[8];    // (4096,)
    float*       out     = (float*)d_out;          // (8,128,32000)

    cudaFuncSetAttribute(gemm_kernel,
                         cudaFuncAttributeMaxDynamicSharedMemorySize, DYN_BYTES);

    convert_kernel<<<CV_BLK, 256>>>(W, dec);
    copy_kernel<<<CP_BLK, 256>>>(dec, src);
    gemm_kernel<<<dim3(8, 250), 256, DYN_BYTES>>>(bgen, out);
    norm_scatter_kernel<<<NROWS, 512>>>(mask, context, tp, action, loc2glo, out);
}